// round 12
// baseline (speedup 1.0000x reference)
#include <cuda_runtime.h>
#include <cuda_fp16.h>
#include <math.h>
#include <stdint.h>

#define B 256
#define T 256
#define D 409
#define H 1024
#define G4H 4096
#define CELL 512
#define KX2 832       // input proj K: [x_hi(416) | x_lo*32(416)]
#define KH2 2048      // recurrence K: [h_hi | h_lo*32]
#define NCTA 128      // persistent CTAs

// ---------------- device scratch ----------------
static __device__ __align__(128) __half g_xstk[(size_t)B * T * KX2];    // ~109 MB
static __device__ __align__(128) __half g_wihstk[(size_t)G4H * KX2];    // seg0=Whi, seg1=Whi/32
static __device__ __align__(128) __half g_whhstk[(size_t)G4H * KH2];    // packed p = hc*4+gate
static __device__ __align__(128) __half g_ha[2][(size_t)B * KH2];       // [hi | lo*32] ping-pong
static __device__ float g_bias[G4H];
static __device__ float g_xg[(size_t)B * T * G4H];                      // 1 GiB, packed cols
static __device__ float g_hfp[(size_t)B * H];
static __device__ float g_hidden[(size_t)B * CELL];
static __device__ unsigned g_barrier_cnt;

__device__ __forceinline__ float sigm(float x) { return 1.0f / (1.0f + expf(-x)); }

// ---------------- PTX helpers (standard PTX, no 'a' features) ----------------
__device__ __forceinline__ uint32_t smem_to_u32(const void* p) {
    uint32_t a;
    asm("{ .reg .u64 t; cvta.to.shared.u64 t, %1; cvt.u32.u64 %0, t; }" : "=r"(a) : "l"(p));
    return a;
}
__device__ __forceinline__ uint32_t swz(uint32_t off) { return off ^ ((off >> 3) & 0x70); }
__device__ __forceinline__ void cpa16(uint32_t dst, const void* src) {
    asm volatile("cp.async.cg.shared.global [%0], [%1], 16;" :: "r"(dst), "l"(src) : "memory");
}
#define CP_COMMIT() asm volatile("cp.async.commit_group;" ::: "memory")
#define CP_WAIT0()  asm volatile("cp.async.wait_group 0;" ::: "memory")
#define CP_WAIT1()  asm volatile("cp.async.wait_group 1;" ::: "memory")

__device__ __forceinline__ void ldsm4(uint32_t& r0, uint32_t& r1, uint32_t& r2, uint32_t& r3,
                                      uint32_t addr) {
    asm volatile("ldmatrix.sync.aligned.m8n8.x4.shared.b16 {%0,%1,%2,%3}, [%4];"
                 : "=r"(r0), "=r"(r1), "=r"(r2), "=r"(r3) : "r"(addr));
}
__device__ __forceinline__ void mma16816(float* c, uint32_t a0, uint32_t a1, uint32_t a2,
                                         uint32_t a3, uint32_t b0, uint32_t b1) {
    asm volatile(
        "mma.sync.aligned.m16n8k16.row.col.f32.f16.f16.f32 "
        "{%0,%1,%2,%3}, {%4,%5,%6,%7}, {%8,%9}, {%0,%1,%2,%3};"
        : "+f"(c[0]), "+f"(c[1]), "+f"(c[2]), "+f"(c[3])
        : "r"(a0), "r"(a1), "r"(a2), "r"(a3), "r"(b0), "r"(b1));
}

#define EPI_STRIDE 132
#define DYN_SMEM_XG 69632
#define STAGE_BYTES 24576                  // A 16KB + B 8KB per stage
#define XG_OFF (3 * STAGE_BYTES)           // xg prefetch buffer
#define XG_ROWB 272                        // 17*16: 16B-aligned row stride
#define DYN_SMEM_LSTM (XG_OFF + 128 * XG_ROWB)   // 108544

// ---------------- split/pack kernels ----------------
// packed row p -> original row r = (p&3)*1024 + (p>>2)   (gate-interleaved)
__global__ void split_whh_kernel(const float* __restrict__ Whh) {
    size_t idx = (size_t)blockIdx.x * blockDim.x + threadIdx.x;
    if (idx >= (size_t)G4H * KH2) return;
    int p = (int)(idx / KH2), k = (int)(idx - (size_t)p * KH2);
    int seg = k >> 10, kk = k & 1023;
    int r = (p & 3) * 1024 + (p >> 2);
    float w = Whh[(size_t)r * H + kk];
    float hif = __half2float(__float2half_rn(w));
    g_whhstk[idx] = (seg == 0) ? __float2half_rn(w) : __float2half_rn(hif * 0.03125f);
}
__global__ void split_wih_kernel(const float* __restrict__ Wih) {
    size_t idx = (size_t)blockIdx.x * blockDim.x + threadIdx.x;
    if (idx >= (size_t)G4H * KX2) return;
    int p = (int)(idx / KX2), kp = (int)(idx - (size_t)p * KX2);
    int seg = kp / 416, d = kp - seg * 416;
    int r = (p & 3) * 1024 + (p >> 2);
    float w = (d < D) ? Wih[(size_t)r * D + d] : 0.0f;
    float hif = __half2float(__float2half_rn(w));
    g_wihstk[idx] = (seg == 0) ? __float2half_rn(w) : __float2half_rn(hif * 0.03125f);
}
__global__ void split_x_kernel(const float* __restrict__ xt, const float* __restrict__ xa,
                               const float* __restrict__ xv) {
    size_t idx = (size_t)blockIdx.x * blockDim.x + threadIdx.x;
    if (idx >= (size_t)B * T * KX2) return;
    int m = (int)(idx / KX2), kp = (int)(idx - (size_t)m * KX2);
    int t = m >> 8, b = m & 255;
    int seg = kp / 416, d = kp - seg * 416;
    float v = 0.0f;
    if (d < 300)      v = xt[((size_t)b * T + t) * 300 + d];
    else if (d < 374) v = xa[((size_t)b * T + t) * 74 + (d - 300)];
    else if (d < 409) v = xv[((size_t)b * T + t) * 35 + (d - 374)];
    __half hi = __float2half_rn(v);
    g_xstk[idx] = (seg == 0) ? hi : __float2half_rn((v - __half2float(hi)) * 32.0f);
}
__global__ void init_kernel(const float* __restrict__ b_ih, const float* __restrict__ b_hh) {
    int idx = blockIdx.x * blockDim.x + threadIdx.x;
    if (idx == 0) g_barrier_cnt = 0u;
    if (idx < G4H) {
        int r = (idx & 3) * 1024 + (idx >> 2);
        g_bias[idx] = b_ih[r] + b_hh[r];
    }
    if (idx < B * KH2) g_ha[0][idx] = __float2half_rn(0.0f);
}

// ---------------- input-projection GEMM ----------------
__device__ __forceinline__ void mma_mainloop_xg(const __half* __restrict__ Ag, size_t lda,
                                                const __half* __restrict__ Bg, size_t ldb,
                                                int NC, char* smem, float acc[4][4][4]) {
    uint32_t sb = smem_to_u32(smem);
    const int tid = threadIdx.x, lane = tid & 31, wid = tid >> 5;
    const int mwo = (wid >> 2) * 64, nwo = (wid & 3) * 32;

    auto load_chunk = [&](int c, int bf) {
        uint32_t ab = sb + bf * 32768, bb = ab + 16384;
        const __half* As = Ag + (size_t)c * 64;
        const __half* Bs = Bg + (size_t)c * 64;
#pragma unroll
        for (int i = 0; i < 4; i++) {
            int f = tid + i * 256, r = f >> 3, j = f & 7;
            cpa16(ab + swz(r * 128 + j * 16), As + (size_t)r * lda + j * 8);
            cpa16(bb + swz(r * 128 + j * 16), Bs + (size_t)r * ldb + j * 8);
        }
        CP_COMMIT();
    };

    load_chunk(0, 0);
    CP_WAIT0();
    __syncthreads();

    const int rowA = mwo + (lane & 15);
    const int koA = ((lane >> 4) & 1) * 16;
    const int rowB = nwo + (lane & 7) + ((lane >> 4) & 1) * 8;
    const int koB = ((lane >> 3) & 1) * 16;

    for (int c = 0; c < NC; c++) {
        int bf = c & 1;
        if (c + 1 < NC) load_chunk(c + 1, bf ^ 1);
        uint32_t ab = sb + bf * 32768, bb = ab + 16384;
#pragma unroll
        for (int s = 0; s < 4; s++) {
            uint32_t areg[4][4];
#pragma unroll
            for (int mi = 0; mi < 4; mi++)
                ldsm4(areg[mi][0], areg[mi][1], areg[mi][2], areg[mi][3],
                      ab + swz((uint32_t)(rowA + mi * 16) * 128 + s * 32 + koA));
            uint32_t breg[8];
            ldsm4(breg[0], breg[1], breg[2], breg[3],
                  bb + swz((uint32_t)rowB * 128 + s * 32 + koB));
            ldsm4(breg[4], breg[5], breg[6], breg[7],
                  bb + swz((uint32_t)(rowB + 16) * 128 + s * 32 + koB));
#pragma unroll
            for (int mi = 0; mi < 4; mi++)
#pragma unroll
                for (int nj = 0; nj < 4; nj++)
                    mma16816(acc[mi][nj], areg[mi][0], areg[mi][1], areg[mi][2], areg[mi][3],
                             breg[nj * 2], breg[nj * 2 + 1]);
        }
        if (c + 1 < NC) { CP_WAIT0(); __syncthreads(); }
    }
    __syncthreads();
}

__global__ void __launch_bounds__(256) gemm_xg_tc() {
    extern __shared__ char smem[];
    const int m0 = blockIdx.y * 128, n0 = blockIdx.x * 128;
    float acc[4][4][4];
#pragma unroll
    for (int a = 0; a < 4; a++)
#pragma unroll
        for (int b = 0; b < 4; b++)
#pragma unroll
            for (int c = 0; c < 4; c++) acc[a][b][c] = 0.0f;

    mma_mainloop_xg(g_xstk + (size_t)m0 * KX2, KX2, g_wihstk + (size_t)n0 * KX2, KX2,
                    KX2 / 64, smem, acc);

    float* epi = (float*)smem;
    {
        const int tid = threadIdx.x, lane = tid & 31, wid = tid >> 5;
        const int mwo = (wid >> 2) * 64, nwo = (wid & 3) * 32;
#pragma unroll
        for (int mi = 0; mi < 4; mi++) {
            int r = mwo + mi * 16 + (lane >> 2);
#pragma unroll
            for (int nj = 0; nj < 4; nj++) {
                int col = nwo + nj * 8 + (lane & 3) * 2;
                *(float2*)&epi[r * EPI_STRIDE + col] = make_float2(acc[mi][nj][0], acc[mi][nj][1]);
                *(float2*)&epi[(r + 8) * EPI_STRIDE + col] = make_float2(acc[mi][nj][2], acc[mi][nj][3]);
            }
        }
    }
    __syncthreads();
    const int tid = threadIdx.x;
#pragma unroll
    for (int i = 0; i < 16; i++) {
        int f = tid + i * 256, r = f >> 5, q = f & 31;
        float4 v = *(float4*)&epi[r * EPI_STRIDE + q * 4];
        float4 bb = *(const float4*)&g_bias[n0 + q * 4];
        v.x += bb.x; v.y += bb.y; v.z += bb.z; v.w += bb.w;
        *(float4*)&g_xg[(size_t)(m0 + r) * G4H + n0 + q * 4] = v;
    }
}

// ---------------- persistent recurrence kernel ----------------
__global__ void __launch_bounds__(256, 1) lstm_persistent() {
    extern __shared__ char smem[];
    uint32_t sb = smem_to_u32(smem);
    const int tid = threadIdx.x, lane = tid & 31, wid = tid >> 5;
    const int bid = blockIdx.x;
    const int m0 = (bid & 1) * 128;          // batch tile
    const int n0 = (bid >> 1) * 64;          // packed-col tile
    const int mwo = (wid >> 1) * 32;
    const int nwo = (wid & 1) * 32;

    const int rowA = mwo + (lane & 15);
    const int koA = ((lane >> 4) & 1) * 16;
    const int rowB = nwo + (lane & 7) + ((lane >> 4) & 1) * 8;
    const int koB = ((lane >> 3) & 1) * 16;

    const int erow_loc = mwo + (lane >> 2) + ((lane & 1) ? 8 : 0);   // + mi*16
    const int ehc_loc = (nwo >> 2) + ((lane >> 1) & 1);              // + nj*2 (local)

    float c_reg[8];
#pragma unroll
    for (int i = 0; i < 8; i++) c_reg[i] = 0.0f;

    const __half* __restrict__ Wbase = g_whhstk + (size_t)n0 * KH2;

    for (int t = 0; t < T; t++) {
        const __half* __restrict__ Abase = g_ha[t & 1] + (size_t)m0 * KH2;
        const float* __restrict__ xg_t = g_xg + (size_t)t * ((size_t)B * G4H);

        auto load_chunk = [&](int c, int s) {
            uint32_t ab = sb + s * STAGE_BYTES, bb = ab + 16384;
            const __half* As = Abase + c * 64;
            const __half* Bs = Wbase + c * 64;
#pragma unroll
            for (int i = 0; i < 4; i++) {
                int f = tid + i * 256, r = f >> 3, j = f & 7;
                cpa16(ab + swz(r * 128 + j * 16), As + (size_t)r * KH2 + j * 8);
            }
#pragma unroll
            for (int i = 0; i < 2; i++) {
                int f = tid + i * 256, r = f >> 3, j = f & 7;
                cpa16(bb + swz(r * 128 + j * 16), Bs + (size_t)r * KH2 + j * 8);
            }
            CP_COMMIT();
        };

        float acc[2][4][4];
#pragma unroll
        for (int a = 0; a < 2; a++)
#pragma unroll
            for (int b = 0; b < 4; b++)
#pragma unroll
                for (int c = 0; c < 4; c++) acc[a][b][c] = 0.0f;

        const int NC = KH2 / 64;   // 32
        // prefetch this step's xg tile (rides chunk-0's commit group)
#pragma unroll
        for (int i = 0; i < 8; i++) {
            int f = tid + i * 256, r = f >> 4, j = f & 15;
            cpa16(sb + XG_OFF + r * XG_ROWB + j * 16,
                  xg_t + (size_t)(m0 + r) * G4H + n0 + j * 4);
        }
        load_chunk(0, 0);
        load_chunk(1, 1);

        for (int c = 0; c < NC; c++) {
            CP_WAIT1();
            __syncthreads();
            if (c + 2 < NC) load_chunk(c + 2, (c + 2) % 3);
            uint32_t ab = sb + (c % 3) * STAGE_BYTES, bb = ab + 16384;
            uint32_t aF[2][2][4], bF[2][8];
            auto ldfrag = [&](int buf, int s) {
#pragma unroll
                for (int mi = 0; mi < 2; mi++)
                    ldsm4(aF[buf][mi][0], aF[buf][mi][1], aF[buf][mi][2], aF[buf][mi][3],
                          ab + swz((uint32_t)(rowA + mi * 16) * 128 + s * 32 + koA));
                ldsm4(bF[buf][0], bF[buf][1], bF[buf][2], bF[buf][3],
                      bb + swz((uint32_t)rowB * 128 + s * 32 + koB));
                ldsm4(bF[buf][4], bF[buf][5], bF[buf][6], bF[buf][7],
                      bb + swz((uint32_t)(rowB + 16) * 128 + s * 32 + koB));
            };
            ldfrag(0, 0);
#pragma unroll
            for (int s = 0; s < 4; s++) {
                const int cur = s & 1;
                if (s < 3) ldfrag(cur ^ 1, s + 1);
#pragma unroll
                for (int mi = 0; mi < 2; mi++)
#pragma unroll
                    for (int nj = 0; nj < 4; nj++)
                        mma16816(acc[mi][nj], aF[cur][mi][0], aF[cur][mi][1],
                                 aF[cur][mi][2], aF[cur][mi][3],
                                 bF[cur][nj * 2], bF[cur][nj * 2 + 1]);
            }
        }

        // ---- register epilogue: shfl gate exchange + LSTM update ----
        {
            __half* __restrict__ ho = g_ha[(t + 1) & 1];
            const bool even = (lane & 1) == 0;
#pragma unroll
            for (int mi = 0; mi < 2; mi++) {
#pragma unroll
                for (int nj = 0; nj < 4; nj++) {
                    float c0 = acc[mi][nj][0], c1 = acc[mi][nj][1];
                    float c2 = acc[mi][nj][2], c3 = acc[mi][nj][3];
                    float p0 = __shfl_xor_sync(0xffffffffu, c0, 1);
                    float p1 = __shfl_xor_sync(0xffffffffu, c1, 1);
                    float p2 = __shfl_xor_sync(0xffffffffu, c2, 1);
                    float p3 = __shfl_xor_sync(0xffffffffu, c3, 1);
                    float pi, pf, pg, po;
                    if (even) { pi = c0; pf = c1; pg = p0; po = p1; }
                    else      { pi = p2; pf = p3; pg = c2; po = c3; }
                    int lm = erow_loc + mi * 16;
                    int b = m0 + lm;
                    int hcl = ehc_loc + nj * 2;
                    int hc = (n0 >> 2) + hcl;
                    float4 xv = *(const float4*)(smem + XG_OFF + (size_t)lm * XG_ROWB + hcl * 16);
                    float gi = sigm(pi + xv.x);
                    float gf = sigm(pf + xv.y);
                    float gg = tanhf(pg + xv.z);
                    float go = sigm(po + xv.w);
                    int ci = mi * 4 + nj;
                    float cn = gf * c_reg[ci] + gi * gg;
                    c_reg[ci] = cn;
                    float hn = go * tanhf(cn);
                    __half hh = __float2half_rn(hn);
                    __half hl = __float2half_rn((hn - __half2float(hh)) * 32.0f);
                    size_t hb = (size_t)b * KH2 + hc;
                    ho[hb] = hh;
                    ho[hb + 1024] = hl;
                    if (t == T - 1) g_hfp[(size_t)b * H + hc] = hn;
                }
            }
        }

        // ---- grid barrier ----
        __syncthreads();
        if (tid == 0) {
            __threadfence();
            atomicAdd(&g_barrier_cnt, 1u);
            unsigned target = (unsigned)NCTA * (unsigned)(t + 1);
            unsigned v;
            do {
                asm volatile("ld.acquire.gpu.b32 %0, [%1];" : "=r"(v) : "l"(&g_barrier_cnt) : "memory");
            } while (v < target);
            __threadfence();
        }
        __syncthreads();
    }
}

// ---------------- MLP head ----------------
__global__ void __launch_bounds__(256) mlp1_kernel(const float* __restrict__ W1,
                                                   const float* __restrict__ b1) {
    __shared__ float As[16][64];
    __shared__ float Bs[16][64];
    const float* __restrict__ hl = g_hfp;
    const int tid = threadIdx.x;
    const int tx = tid & 15, ty = tid >> 4;
    const int b0 = blockIdx.y * 64, c0 = blockIdx.x * 64;
    float acc[4][4];
#pragma unroll
    for (int i = 0; i < 4; i++)
#pragma unroll
        for (int j = 0; j < 4; j++) acc[i][j] = 0.0f;
    const int lr = tid >> 2, lc = (tid & 3) << 2;
    for (int k0 = 0; k0 < H; k0 += 16) {
        float4 va = *(const float4*)&hl[(size_t)(b0 + lr) * H + k0 + lc];
        As[lc + 0][lr] = va.x; As[lc + 1][lr] = va.y; As[lc + 2][lr] = va.z; As[lc + 3][lr] = va.w;
        float4 vb = *(const float4*)&W1[(size_t)(c0 + lr) * H + k0 + lc];
        Bs[lc + 0][lr] = vb.x; Bs[lc + 1][lr] = vb.y; Bs[lc + 2][lr] = vb.z; Bs[lc + 3][lr] = vb.w;
        __syncthreads();
#pragma unroll
        for (int k = 0; k < 16; k++) {
            float a[4], b[4];
#pragma unroll
            for (int i = 0; i < 4; i++) a[i] = As[k][ty + 16 * i];
#pragma unroll
            for (int j = 0; j < 4; j++) b[j] = Bs[k][tx + 16 * j];
#pragma unroll
            for (int i = 0; i < 4; i++)
#pragma unroll
                for (int j = 0; j < 4; j++) acc[i][j] += a[i] * b[j];
        }
        __syncthreads();
    }
#pragma unroll
    for (int i = 0; i < 4; i++) {
        int bb = b0 + ty + 16 * i;
#pragma unroll
        for (int j = 0; j < 4; j++) {
            int cc = c0 + tx + 16 * j;
            float v = acc[i][j] + b1[cc];
            g_hidden[(size_t)bb * CELL + cc] = v > 0.0f ? v : 0.0f;
        }
    }
}
__global__ void __launch_bounds__(128) mlp2_kernel(const float* __restrict__ W2,
                                                   const float* __restrict__ b2,
                                                   float* __restrict__ out) {
    int b = blockIdx.x, tid = threadIdx.x;
    float s = 0.0f;
    for (int k = tid; k < CELL; k += 128) s += g_hidden[(size_t)b * CELL + k] * W2[k];
#pragma unroll
    for (int o = 16; o > 0; o >>= 1) s += __shfl_down_sync(0xffffffffu, s, o);
    __shared__ float ws[4];
    if ((tid & 31) == 0) ws[tid >> 5] = s;
    __syncthreads();
    if (tid == 0) out[b] = ws[0] + ws[1] + ws[2] + ws[3] + b2[0];
}

// ---------------- entry point ----------------
extern "C" void kernel_launch(void* const* d_in, const int* in_sizes, int n_in,
                              void* d_out, int out_size) {
    const float* x_text   = (const float*)d_in[0];
    const float* x_audio  = (const float*)d_in[1];
    const float* x_vision = (const float*)d_in[2];
    const float* W_ih     = (const float*)d_in[3];
    const float* W_hh     = (const float*)d_in[4];
    const float* b_ih     = (const float*)d_in[5];
    const float* b_hh     = (const float*)d_in[6];
    const float* W1       = (const float*)d_in[7];
    const float* b1       = (const float*)d_in[8];
    const float* W2       = (const float*)d_in[9];
    const float* b2       = (const float*)d_in[10];
    float* out = (float*)d_out;

    static int attr_done = 0;
    if (!attr_done) {
        cudaFuncSetAttribute(gemm_xg_tc, cudaFuncAttributeMaxDynamicSharedMemorySize, DYN_SMEM_XG);
        cudaFuncSetAttribute(lstm_persistent, cudaFuncAttributeMaxDynamicSharedMemorySize, DYN_SMEM_LSTM);
        attr_done = 1;
    }

    split_whh_kernel<<<(int)(((size_t)G4H * KH2 + 255) / 256), 256>>>(W_hh);
    split_wih_kernel<<<(int)(((size_t)G4H * KX2 + 255) / 256), 256>>>(W_ih);
    split_x_kernel<<<(int)(((size_t)B * T * KX2 + 255) / 256), 256>>>(x_text, x_audio, x_vision);
    init_kernel<<<(B * KH2 + 255) / 256, 256>>>(b_ih, b_hh);

    gemm_xg_tc<<<dim3(G4H / 128, (B * T) / 128), 256, DYN_SMEM_XG>>>();

    lstm_persistent<<<NCTA, 256, DYN_SMEM_LSTM>>>();

    mlp1_kernel<<<dim3(CELL / 64, B / 64), 256>>>(W1, b1);
    mlp2_kernel<<<B, 128>>>(W2, b2, out);
}

// round 13
// speedup vs baseline: 1.0016x; 1.0016x over previous
#include <cuda_runtime.h>
#include <cuda_fp16.h>
#include <math.h>
#include <stdint.h>

#define B 256
#define T 256
#define D 409
#define H 1024
#define G4H 4096
#define CELL 512
#define KX2 832       // input proj K: [x_hi(416) | x_lo*32(416)]
#define KH2 2048      // recurrence K: [h_hi | h_lo*32]
#define NCTA 128      // persistent CTAs

// ---------------- device scratch ----------------
static __device__ __align__(128) __half g_xstk[(size_t)B * T * KX2];    // ~109 MB
static __device__ __align__(128) __half g_wihstk[(size_t)G4H * KX2];    // seg0=Whi, seg1=Whi/32
static __device__ __align__(128) __half g_whhstk[(size_t)G4H * KH2];    // packed p = hc*4+gate
static __device__ __align__(128) __half g_ha[2][(size_t)B * KH2];       // [hi | lo*32] ping-pong
static __device__ float g_bias[G4H];
static __device__ float g_xg[(size_t)B * T * G4H];                      // 1 GiB, packed cols
static __device__ float g_hfp[(size_t)B * H];
static __device__ float g_hidden[(size_t)B * CELL];
static __device__ unsigned g_barrier_cnt;

__device__ __forceinline__ float sigm(float x) { return 1.0f / (1.0f + expf(-x)); }

// ---------------- PTX helpers (standard PTX, no 'a' features) ----------------
__device__ __forceinline__ uint32_t smem_to_u32(const void* p) {
    uint32_t a;
    asm("{ .reg .u64 t; cvta.to.shared.u64 t, %1; cvt.u32.u64 %0, t; }" : "=r"(a) : "l"(p));
    return a;
}
__device__ __forceinline__ uint32_t swz(uint32_t off) { return off ^ ((off >> 3) & 0x70); }
__device__ __forceinline__ void cpa16(uint32_t dst, const void* src) {
    asm volatile("cp.async.cg.shared.global [%0], [%1], 16;" :: "r"(dst), "l"(src) : "memory");
}
#define CP_COMMIT() asm volatile("cp.async.commit_group;" ::: "memory")
#define CP_WAIT0()  asm volatile("cp.async.wait_group 0;" ::: "memory")
#define CP_WAIT1()  asm volatile("cp.async.wait_group 1;" ::: "memory")

__device__ __forceinline__ void ldsm4(uint32_t& r0, uint32_t& r1, uint32_t& r2, uint32_t& r3,
                                      uint32_t addr) {
    asm volatile("ldmatrix.sync.aligned.m8n8.x4.shared.b16 {%0,%1,%2,%3}, [%4];"
                 : "=r"(r0), "=r"(r1), "=r"(r2), "=r"(r3) : "r"(addr));
}
__device__ __forceinline__ void mma16816(float* c, uint32_t a0, uint32_t a1, uint32_t a2,
                                         uint32_t a3, uint32_t b0, uint32_t b1) {
    asm volatile(
        "mma.sync.aligned.m16n8k16.row.col.f32.f16.f16.f32 "
        "{%0,%1,%2,%3}, {%4,%5,%6,%7}, {%8,%9}, {%0,%1,%2,%3};"
        : "+f"(c[0]), "+f"(c[1]), "+f"(c[2]), "+f"(c[3])
        : "r"(a0), "r"(a1), "r"(a2), "r"(a3), "r"(b0), "r"(b1));
}

#define EPI_STRIDE 132
#define DYN_SMEM_XG 69632
#define STAGE_BYTES 24576                  // A 16KB + B 8KB per stage
#define XG_OFF (3 * STAGE_BYTES)           // xg prefetch buffer
#define XG_ROWB 272                        // 17*16: 16B-aligned row stride
#define DYN_SMEM_LSTM (XG_OFF + 128 * XG_ROWB)   // 108544

// ---------------- split/pack kernels ----------------
// packed row p -> original row r = (p&3)*1024 + (p>>2)   (gate-interleaved)
__global__ void split_whh_kernel(const float* __restrict__ Whh) {
    size_t idx = (size_t)blockIdx.x * blockDim.x + threadIdx.x;
    if (idx >= (size_t)G4H * KH2) return;
    int p = (int)(idx / KH2), k = (int)(idx - (size_t)p * KH2);
    int seg = k >> 10, kk = k & 1023;
    int r = (p & 3) * 1024 + (p >> 2);
    float w = Whh[(size_t)r * H + kk];
    float hif = __half2float(__float2half_rn(w));
    g_whhstk[idx] = (seg == 0) ? __float2half_rn(w) : __float2half_rn(hif * 0.03125f);
}
__global__ void split_wih_kernel(const float* __restrict__ Wih) {
    size_t idx = (size_t)blockIdx.x * blockDim.x + threadIdx.x;
    if (idx >= (size_t)G4H * KX2) return;
    int p = (int)(idx / KX2), kp = (int)(idx - (size_t)p * KX2);
    int seg = kp / 416, d = kp - seg * 416;
    int r = (p & 3) * 1024 + (p >> 2);
    float w = (d < D) ? Wih[(size_t)r * D + d] : 0.0f;
    float hif = __half2float(__float2half_rn(w));
    g_wihstk[idx] = (seg == 0) ? __float2half_rn(w) : __float2half_rn(hif * 0.03125f);
}
__global__ void split_x_kernel(const float* __restrict__ xt, const float* __restrict__ xa,
                               const float* __restrict__ xv) {
    size_t idx = (size_t)blockIdx.x * blockDim.x + threadIdx.x;
    if (idx >= (size_t)B * T * KX2) return;
    int m = (int)(idx / KX2), kp = (int)(idx - (size_t)m * KX2);
    int t = m >> 8, b = m & 255;
    int seg = kp / 416, d = kp - seg * 416;
    float v = 0.0f;
    if (d < 300)      v = xt[((size_t)b * T + t) * 300 + d];
    else if (d < 374) v = xa[((size_t)b * T + t) * 74 + (d - 300)];
    else if (d < 409) v = xv[((size_t)b * T + t) * 35 + (d - 374)];
    __half hi = __float2half_rn(v);
    g_xstk[idx] = (seg == 0) ? hi : __float2half_rn((v - __half2float(hi)) * 32.0f);
}
__global__ void init_kernel(const float* __restrict__ b_ih, const float* __restrict__ b_hh) {
    int idx = blockIdx.x * blockDim.x + threadIdx.x;
    if (idx == 0) g_barrier_cnt = 0u;
    if (idx < G4H) {
        int r = (idx & 3) * 1024 + (idx >> 2);
        g_bias[idx] = b_ih[r] + b_hh[r];
    }
    if (idx < B * KH2) g_ha[0][idx] = __float2half_rn(0.0f);
}

// ---------------- input-projection GEMM ----------------
__device__ __forceinline__ void mma_mainloop_xg(const __half* __restrict__ Ag, size_t lda,
                                                const __half* __restrict__ Bg, size_t ldb,
                                                int NC, char* smem, float acc[4][4][4]) {
    uint32_t sb = smem_to_u32(smem);
    const int tid = threadIdx.x, lane = tid & 31, wid = tid >> 5;
    const int mwo = (wid >> 2) * 64, nwo = (wid & 3) * 32;

    auto load_chunk = [&](int c, int bf) {
        uint32_t ab = sb + bf * 32768, bb = ab + 16384;
        const __half* As = Ag + (size_t)c * 64;
        const __half* Bs = Bg + (size_t)c * 64;
#pragma unroll
        for (int i = 0; i < 4; i++) {
            int f = tid + i * 256, r = f >> 3, j = f & 7;
            cpa16(ab + swz(r * 128 + j * 16), As + (size_t)r * lda + j * 8);
            cpa16(bb + swz(r * 128 + j * 16), Bs + (size_t)r * ldb + j * 8);
        }
        CP_COMMIT();
    };

    load_chunk(0, 0);
    CP_WAIT0();
    __syncthreads();

    const int rowA = mwo + (lane & 15);
    const int koA = ((lane >> 4) & 1) * 16;
    const int rowB = nwo + (lane & 7) + ((lane >> 4) & 1) * 8;
    const int koB = ((lane >> 3) & 1) * 16;

    for (int c = 0; c < NC; c++) {
        int bf = c & 1;
        if (c + 1 < NC) load_chunk(c + 1, bf ^ 1);
        uint32_t ab = sb + bf * 32768, bb = ab + 16384;
#pragma unroll
        for (int s = 0; s < 4; s++) {
            uint32_t areg[4][4];
#pragma unroll
            for (int mi = 0; mi < 4; mi++)
                ldsm4(areg[mi][0], areg[mi][1], areg[mi][2], areg[mi][3],
                      ab + swz((uint32_t)(rowA + mi * 16) * 128 + s * 32 + koA));
            uint32_t breg[8];
            ldsm4(breg[0], breg[1], breg[2], breg[3],
                  bb + swz((uint32_t)rowB * 128 + s * 32 + koB));
            ldsm4(breg[4], breg[5], breg[6], breg[7],
                  bb + swz((uint32_t)(rowB + 16) * 128 + s * 32 + koB));
#pragma unroll
            for (int mi = 0; mi < 4; mi++)
#pragma unroll
                for (int nj = 0; nj < 4; nj++)
                    mma16816(acc[mi][nj], areg[mi][0], areg[mi][1], areg[mi][2], areg[mi][3],
                             breg[nj * 2], breg[nj * 2 + 1]);
        }
        if (c + 1 < NC) { CP_WAIT0(); __syncthreads(); }
    }
    __syncthreads();
}

__global__ void __launch_bounds__(256) gemm_xg_tc() {
    extern __shared__ char smem[];
    const int m0 = blockIdx.y * 128, n0 = blockIdx.x * 128;
    float acc[4][4][4];
#pragma unroll
    for (int a = 0; a < 4; a++)
#pragma unroll
        for (int b = 0; b < 4; b++)
#pragma unroll
            for (int c = 0; c < 4; c++) acc[a][b][c] = 0.0f;

    mma_mainloop_xg(g_xstk + (size_t)m0 * KX2, KX2, g_wihstk + (size_t)n0 * KX2, KX2,
                    KX2 / 64, smem, acc);

    float* epi = (float*)smem;
    {
        const int tid = threadIdx.x, lane = tid & 31, wid = tid >> 5;
        const int mwo = (wid >> 2) * 64, nwo = (wid & 3) * 32;
#pragma unroll
        for (int mi = 0; mi < 4; mi++) {
            int r = mwo + mi * 16 + (lane >> 2);
#pragma unroll
            for (int nj = 0; nj < 4; nj++) {
                int col = nwo + nj * 8 + (lane & 3) * 2;
                *(float2*)&epi[r * EPI_STRIDE + col] = make_float2(acc[mi][nj][0], acc[mi][nj][1]);
                *(float2*)&epi[(r + 8) * EPI_STRIDE + col] = make_float2(acc[mi][nj][2], acc[mi][nj][3]);
            }
        }
    }
    __syncthreads();
    const int tid = threadIdx.x;
#pragma unroll
    for (int i = 0; i < 16; i++) {
        int f = tid + i * 256, r = f >> 5, q = f & 31;
        float4 v = *(float4*)&epi[r * EPI_STRIDE + q * 4];
        float4 bb = *(const float4*)&g_bias[n0 + q * 4];
        v.x += bb.x; v.y += bb.y; v.z += bb.z; v.w += bb.w;
        *(float4*)&g_xg[(size_t)(m0 + r) * G4H + n0 + q * 4] = v;
    }
}

// ---------------- persistent recurrence kernel ----------------
__global__ void __launch_bounds__(256, 1) lstm_persistent() {
    extern __shared__ char smem[];
    uint32_t sb = smem_to_u32(smem);
    const int tid = threadIdx.x, lane = tid & 31, wid = tid >> 5;
    const int bid = blockIdx.x;
    const int m0 = (bid & 1) * 128;          // batch tile
    const int n0 = (bid >> 1) * 64;          // packed-col tile
    const int mwo = (wid >> 1) * 32;
    const int nwo = (wid & 1) * 32;

    const int rowA = mwo + (lane & 15);
    const int koA = ((lane >> 4) & 1) * 16;
    const int rowB = nwo + (lane & 7) + ((lane >> 4) & 1) * 8;
    const int koB = ((lane >> 3) & 1) * 16;

    const int erow_loc = mwo + (lane >> 2) + ((lane & 1) ? 8 : 0);   // + mi*16
    const int ehc_loc = (nwo >> 2) + ((lane >> 1) & 1);              // + nj*2 (local)

    float c_reg[8];
#pragma unroll
    for (int i = 0; i < 8; i++) c_reg[i] = 0.0f;

    const __half* __restrict__ Wbase = g_whhstk + (size_t)n0 * KH2;

    for (int t = 0; t < T; t++) {
        const __half* __restrict__ Abase = g_ha[t & 1] + (size_t)m0 * KH2;
        const float* __restrict__ xg_t = g_xg + (size_t)t * ((size_t)B * G4H);

        auto load_chunk = [&](int c, int s) {
            uint32_t ab = sb + s * STAGE_BYTES, bb = ab + 16384;
            const __half* As = Abase + c * 64;
            const __half* Bs = Wbase + c * 64;
#pragma unroll
            for (int i = 0; i < 4; i++) {
                int f = tid + i * 256, r = f >> 3, j = f & 7;
                cpa16(ab + swz(r * 128 + j * 16), As + (size_t)r * KH2 + j * 8);
            }
#pragma unroll
            for (int i = 0; i < 2; i++) {
                int f = tid + i * 256, r = f >> 3, j = f & 7;
                cpa16(bb + swz(r * 128 + j * 16), Bs + (size_t)r * KH2 + j * 8);
            }
            CP_COMMIT();
        };

        float acc[2][4][4];
#pragma unroll
        for (int a = 0; a < 2; a++)
#pragma unroll
            for (int b = 0; b < 4; b++)
#pragma unroll
                for (int c = 0; c < 4; c++) acc[a][b][c] = 0.0f;

        const int NC = KH2 / 64;   // 32
        // prefetch this step's xg tile (rides chunk-0's commit group)
#pragma unroll
        for (int i = 0; i < 8; i++) {
            int f = tid + i * 256, r = f >> 4, j = f & 15;
            cpa16(sb + XG_OFF + r * XG_ROWB + j * 16,
                  xg_t + (size_t)(m0 + r) * G4H + n0 + j * 4);
        }
        load_chunk(0, 0);
        load_chunk(1, 1);

        for (int c = 0; c < NC; c++) {
            CP_WAIT1();
            __syncthreads();
            if (c + 2 < NC) load_chunk(c + 2, (c + 2) % 3);
            uint32_t ab = sb + (c % 3) * STAGE_BYTES, bb = ab + 16384;
            uint32_t aF[2][2][4], bF[2][8];
            auto ldfrag = [&](int buf, int s) {
#pragma unroll
                for (int mi = 0; mi < 2; mi++)
                    ldsm4(aF[buf][mi][0], aF[buf][mi][1], aF[buf][mi][2], aF[buf][mi][3],
                          ab + swz((uint32_t)(rowA + mi * 16) * 128 + s * 32 + koA));
                ldsm4(bF[buf][0], bF[buf][1], bF[buf][2], bF[buf][3],
                      bb + swz((uint32_t)rowB * 128 + s * 32 + koB));
                ldsm4(bF[buf][4], bF[buf][5], bF[buf][6], bF[buf][7],
                      bb + swz((uint32_t)(rowB + 16) * 128 + s * 32 + koB));
            };
            ldfrag(0, 0);
#pragma unroll
            for (int s = 0; s < 4; s++) {
                const int cur = s & 1;
                if (s < 3) ldfrag(cur ^ 1, s + 1);
#pragma unroll
                for (int mi = 0; mi < 2; mi++)
#pragma unroll
                    for (int nj = 0; nj < 4; nj++)
                        mma16816(acc[mi][nj], aF[cur][mi][0], aF[cur][mi][1],
                                 aF[cur][mi][2], aF[cur][mi][3],
                                 bF[cur][nj * 2], bF[cur][nj * 2 + 1]);
            }
        }

        // ---- register epilogue: shfl gate exchange + LSTM update ----
        {
            __half* __restrict__ ho = g_ha[(t + 1) & 1];
            const bool even = (lane & 1) == 0;
#pragma unroll
            for (int mi = 0; mi < 2; mi++) {
#pragma unroll
                for (int nj = 0; nj < 4; nj++) {
                    float c0 = acc[mi][nj][0], c1 = acc[mi][nj][1];
                    float c2 = acc[mi][nj][2], c3 = acc[mi][nj][3];
                    float p0 = __shfl_xor_sync(0xffffffffu, c0, 1);
                    float p1 = __shfl_xor_sync(0xffffffffu, c1, 1);
                    float p2 = __shfl_xor_sync(0xffffffffu, c2, 1);
                    float p3 = __shfl_xor_sync(0xffffffffu, c3, 1);
                    float pi, pf, pg, po;
                    if (even) { pi = c0; pf = c1; pg = p0; po = p1; }
                    else      { pi = p2; pf = p3; pg = c2; po = c3; }
                    int lm = erow_loc + mi * 16;
                    int b = m0 + lm;
                    int hcl = ehc_loc + nj * 2;
                    int hc = (n0 >> 2) + hcl;
                    float4 xv = *(const float4*)(smem + XG_OFF + (size_t)lm * XG_ROWB + hcl * 16);
                    float gi = sigm(pi + xv.x);
                    float gf = sigm(pf + xv.y);
                    float gg = tanhf(pg + xv.z);
                    float go = sigm(po + xv.w);
                    int ci = mi * 4 + nj;
                    float cn = gf * c_reg[ci] + gi * gg;
                    c_reg[ci] = cn;
                    float hn = go * tanhf(cn);
                    __half hh = __float2half_rn(hn);
                    __half hl = __float2half_rn((hn - __half2float(hh)) * 32.0f);
                    size_t hb = (size_t)b * KH2 + hc;
                    ho[hb] = hh;
                    ho[hb + 1024] = hl;
                    if (t == T - 1) g_hfp[(size_t)b * H + hc] = hn;
                }
            }
        }

        // ---- grid barrier ----
        __syncthreads();
        if (tid == 0) {
            __threadfence();
            atomicAdd(&g_barrier_cnt, 1u);
            unsigned target = (unsigned)NCTA * (unsigned)(t + 1);
            unsigned v;
            do {
                asm volatile("ld.acquire.gpu.b32 %0, [%1];" : "=r"(v) : "l"(&g_barrier_cnt) : "memory");
            } while (v < target);
            __threadfence();
        }
        __syncthreads();
    }
}

// ---------------- MLP head ----------------
__global__ void __launch_bounds__(256) mlp1_kernel(const float* __restrict__ W1,
                                                   const float* __restrict__ b1) {
    __shared__ float As[16][64];
    __shared__ float Bs[16][64];
    const float* __restrict__ hl = g_hfp;
    const int tid = threadIdx.x;
    const int tx = tid & 15, ty = tid >> 4;
    const int b0 = blockIdx.y * 64, c0 = blockIdx.x * 64;
    float acc[4][4];
#pragma unroll
    for (int i = 0; i < 4; i++)
#pragma unroll
        for (int j = 0; j < 4; j++) acc[i][j] = 0.0f;
    const int lr = tid >> 2, lc = (tid & 3) << 2;
    for (int k0 = 0; k0 < H; k0 += 16) {
        float4 va = *(const float4*)&hl[(size_t)(b0 + lr) * H + k0 + lc];
        As[lc + 0][lr] = va.x; As[lc + 1][lr] = va.y; As[lc + 2][lr] = va.z; As[lc + 3][lr] = va.w;
        float4 vb = *(const float4*)&W1[(size_t)(c0 + lr) * H + k0 + lc];
        Bs[lc + 0][lr] = vb.x; Bs[lc + 1][lr] = vb.y; Bs[lc + 2][lr] = vb.z; Bs[lc + 3][lr] = vb.w;
        __syncthreads();
#pragma unroll
        for (int k = 0; k < 16; k++) {
            float a[4], b[4];
#pragma unroll
            for (int i = 0; i < 4; i++) a[i] = As[k][ty + 16 * i];
#pragma unroll
            for (int j = 0; j < 4; j++) b[j] = Bs[k][tx + 16 * j];
#pragma unroll
            for (int i = 0; i < 4; i++)
#pragma unroll
                for (int j = 0; j < 4; j++) acc[i][j] += a[i] * b[j];
        }
        __syncthreads();
    }
#pragma unroll
    for (int i = 0; i < 4; i++) {
        int bb = b0 + ty + 16 * i;
#pragma unroll
        for (int j = 0; j < 4; j++) {
            int cc = c0 + tx + 16 * j;
            float v = acc[i][j] + b1[cc];
            g_hidden[(size_t)bb * CELL + cc] = v > 0.0f ? v : 0.0f;
        }
    }
}
__global__ void __launch_bounds__(128) mlp2_kernel(const float* __restrict__ W2,
                                                   const float* __restrict__ b2,
                                                   float* __restrict__ out) {
    int b = blockIdx.x, tid = threadIdx.x;
    float s = 0.0f;
    for (int k = tid; k < CELL; k += 128) s += g_hidden[(size_t)b * CELL + k] * W2[k];
#pragma unroll
    for (int o = 16; o > 0; o >>= 1) s += __shfl_down_sync(0xffffffffu, s, o);
    __shared__ float ws[4];
    if ((tid & 31) == 0) ws[tid >> 5] = s;
    __syncthreads();
    if (tid == 0) out[b] = ws[0] + ws[1] + ws[2] + ws[3] + b2[0];
}

// ---------------- entry point ----------------
extern "C" void kernel_launch(void* const* d_in, const int* in_sizes, int n_in,
                              void* d_out, int out_size) {
    const float* x_text   = (const float*)d_in[0];
    const float* x_audio  = (const float*)d_in[1];
    const float* x_vision = (const float*)d_in[2];
    const float* W_ih     = (const float*)d_in[3];
    const float* W_hh     = (const float*)d_in[4];
    const float* b_ih     = (const float*)d_in[5];
    const float* b_hh     = (const float*)d_in[6];
    const float* W1       = (const float*)d_in[7];
    const float* b1       = (const float*)d_in[8];
    const float* W2       = (const float*)d_in[9];
    const float* b2       = (const float*)d_in[10];
    float* out = (float*)d_out;

    static int attr_done = 0;
    if (!attr_done) {
        cudaFuncSetAttribute(gemm_xg_tc, cudaFuncAttributeMaxDynamicSharedMemorySize, DYN_SMEM_XG);
        cudaFuncSetAttribute(lstm_persistent, cudaFuncAttributeMaxDynamicSharedMemorySize, DYN_SMEM_LSTM);
        attr_done = 1;
    }

    split_whh_kernel<<<(int)(((size_t)G4H * KH2 + 255) / 256), 256>>>(W_hh);
    split_wih_kernel<<<(int)(((size_t)G4H * KX2 + 255) / 256), 256>>>(W_ih);
    split_x_kernel<<<(int)(((size_t)B * T * KX2 + 255) / 256), 256>>>(x_text, x_audio, x_vision);
    init_kernel<<<(B * KH2 + 255) / 256, 256>>>(b_ih, b_hh);

    gemm_xg_tc<<<dim3(G4H / 128, (B * T) / 128), 256, DYN_SMEM_XG>>>();

    lstm_persistent<<<NCTA, 256, DYN_SMEM_LSTM>>>();

    mlp1_kernel<<<dim3(CELL / 64, B / 64), 256>>>(W1, b1);
    mlp2_kernel<<<B, 128>>>(W2, b2, out);
}